// round 8
// baseline (speedup 1.0000x reference)
#include <cuda_runtime.h>

#define BB 2
#define DD 64
#define HH 128
#define WW 128
#define NS (BB*DD)      // 128 slices
#define BPS 2           // blocks per slice
#define NBLK (NS*BPS)   // 256 blocks
#define NT 1024
#define NWARP 32
#define OROWS 64        // owned rows per block
#define GR 10           // halo/guard rows each side
#define SROWS (OROWS + 2*GR)   // 84 packed rows
#define SSTR 6          // words per packed row: [guard, W0..W3, guard]

struct E4  { signed char dr, dc; short pad; };
struct Grp { short start; short cnt; float sv; };

constexpr int count_tab() {
    int n = 0;
    for (int dr = -9; dr <= 9; ++dr)
        for (int dc = -9; dc <= 9; ++dc) {
            int d2 = dr * dr + dc * dc;
            if (d2 >= 1 && d2 <= 99) ++n;
        }
    return n;
}
constexpr int TABN = count_tab();           // 304
constexpr int count_groups() {
    int n = 0;
    for (int d2 = 1; d2 <= 99; ++d2) {
        bool any = false;
        for (int dr = -9; dr <= 9 && !any; ++dr)
            for (int dc = -9; dc <= 9; ++dc)
                if (dr * dr + dc * dc == d2) { any = true; break; }
        if (any) ++n;
    }
    return n;
}
constexpr int NG = count_groups();

constexpr double csqrt_(double x) {
    double g = x > 1.0 ? x : 1.0;
    for (int i = 0; i < 60; ++i) g = 0.5 * (g + x / g);
    return g;
}
struct ETab { E4 e[TABN]; };
struct GTab { Grp g[NG]; };
constexpr ETab make_e() {
    ETab t{}; int n = 0;
    for (int d2 = 1; d2 <= 99; ++d2)
        for (int dr = -9; dr <= 9; ++dr)
            for (int dc = -9; dc <= 9; ++dc)
                if (dr * dr + dc * dc == d2) {
                    t.e[n].dr = (signed char)dr; t.e[n].dc = (signed char)dc;
                    t.e[n].pad = 0; ++n;
                }
    return t;
}
constexpr GTab make_g() {
    GTab t{}; int n = 0, gi = 0;
    for (int d2 = 1; d2 <= 99; ++d2) {
        int start = n;
        for (int dr = -9; dr <= 9; ++dr)
            for (int dc = -9; dc <= 9; ++dc)
                if (dr * dr + dc * dc == d2) ++n;
        if (n > start) {
            t.g[gi].start = (short)start; t.g[gi].cnt = (short)(n - start);
            t.g[gi].sv = (float)csqrt_((double)d2); ++gi;
        }
    }
    return t;
}
__constant__ ETab C_E = make_e();
__constant__ GTab C_G = make_g();

__device__ volatile float g_part_sum[NBLK];
__device__ volatile float g_part_cnt[NBLK];
__device__ volatile int   g_part_fg[NBLK];
__device__ unsigned int   g_done = 0;

// combined(px) = dist to nearest opposite-valued pixel (s binary => one EDT
// term always zero), clamped at 10. Bit-parallel: rows packed into 128-bit
// masks; per offset the opposite mask for 32 pixels is one xor of a funnel-
// shifted neighbor row. Offsets walked in ascending-d2 groups; each group's
// entries are split across a 4-lane quad (partial gor merged by 2 quad-scoped
// shfl_xor), quadrupling warp parallelism. found seeded with ~y_true; exit
// when every y_true pixel of the word is resolved; unfound pixels contribute
// exactly the clamp value 10. Finalize fused via last-block atomic counter.
__global__ __launch_bounds__(NT, 2)
void edt_kernel(const float* __restrict__ yp, const float* __restrict__ yt,
                float* __restrict__ out)
{
    __shared__ unsigned sS[SROWS][SSTR];
    __shared__ unsigned sY[OROWS][4];
    __shared__ E4  sE[TABN];
    __shared__ Grp sG[NG];
    __shared__ float wsum[NWARP], wcnt[NWARP];
    __shared__ int s_islast;
    __shared__ unsigned s_fgw[4];
    __shared__ int s_first[BB], s_last[BB];

    const int blk   = blockIdx.x;
    const int slice = blk >> 1;
    const int R0    = (blk & 1) * OROWS;
    const int t     = threadIdx.x;
    const int lane  = t & 31, wp = t >> 5;
    const float* yps = yp + (size_t)slice * HH * WW;
    const float* yts = yt + (size_t)slice * HH * WW;

    // copy tables to smem (constant cache would serialize on divergent quads)
    if (t < TABN) sE[t] = C_E.e[t];
    if (t < NG)   sG[t] = C_G.g[t];
    if (t < SROWS) { sS[t][0] = 0u; sS[t][5] = 0u; }   // guard word columns

    // pack phase: one warp-ballot per (row, word); rows outside [0,HH) -> 0
    for (int task = wp; task < SROWS * 4; task += NWARP) {
        int rr = task >> 2, w = task & 3;
        int grow = R0 - GR + rr;
        unsigned m = 0u;
        if ((unsigned)grow < (unsigned)HH)
            m = __ballot_sync(0xffffffffu, yps[grow * WW + w * 32 + lane] > 0.7f);
        if (lane == 0) sS[rr][1 + w] = m;
    }
    for (int task = wp; task < OROWS * 4; task += NWARP) {
        int rr = task >> 2, w = task & 3;
        unsigned m = __ballot_sync(0xffffffffu,
                                   yts[(R0 + rr) * WW + w * 32 + lane] != 0.0f);
        if (lane == 0) sY[rr][w] = m;
    }
    __syncthreads();

    // main phase: 4-lane quad <-> one (row, word); sub splits group entries
    const int sub = t & 3;
    const int g   = t >> 2;            // 0..255
    const int rl  = g >> 2;            // local row 0..63
    const int w   = g & 3;
    const unsigned self = sS[GR + rl][1 + w];
    const unsigned ytm  = sY[rl][w];
    const unsigned* rowbase = &sS[GR + rl][0];
    const int grb = R0 + rl;           // global row of this word
    const unsigned qmask = 0xFu << ((lane >> 2) << 2);
    int fgflag = (self != 0u);
    unsigned found = ~ytm;             // non-y_true pixels are don't-care
    unsigned gor = 0u;
    float sum = 0.0f;

    #pragma unroll 1
    for (int gi = 0; gi < NG; ++gi) {
        Grp G = sG[gi];
        #pragma unroll 1
        for (int k = G.start + sub; k < G.start + G.cnt; k += 4) {
            E4 e = sE[k];
            const unsigned* rw = rowbase + (int)e.dr * SSTR;
            int dc = e.dc;
            unsigned sh, valid;
            if (dc >= 0) {
                sh = __funnelshift_r(rw[1 + w], rw[2 + w], dc);
                valid = (w == 3) ? (0xffffffffu >> dc) : 0xffffffffu;
            } else {
                int kk = -dc;
                sh = __funnelshift_l(rw[w], rw[1 + w], kk);
                valid = (w == 0) ? (0xffffffffu << kk) : 0xffffffffu;
            }
            unsigned rv = ((unsigned)(grb + e.dr) < (unsigned)HH) ? 0xffffffffu : 0u;
            gor |= (self ^ sh) & valid & rv;
        }
        gor |= __shfl_xor_sync(qmask, gor, 1);
        gor |= __shfl_xor_sync(qmask, gor, 2);
        unsigned nw = gor & ~found;
        if (nw) { sum += G.sv * (float)__popc(nw); found |= nw; }
        if (found == 0xffffffffu) break;
    }
    sum += 10.0f * (float)__popc(~found);   // unfound => dist >= 10 => clamp
    float cntf = (float)__popc(ytm);
    if (sub) { sum = 0.0f; cntf = 0.0f; }   // quad computed identical results
    int anyfg = __syncthreads_or(fgflag);

    // block reduction (32 warps)
    #pragma unroll
    for (int o = 16; o > 0; o >>= 1) {
        sum  += __shfl_down_sync(0xffffffffu, sum,  o);
        cntf += __shfl_down_sync(0xffffffffu, cntf, o);
    }
    if (lane == 0) { wsum[wp] = sum; wcnt[wp] = cntf; }
    __syncthreads();
    if (t == 0) {
        float s = 0.0f, c = 0.0f;
        #pragma unroll
        for (int i = 0; i < NWARP; i++) { s += wsum[i]; c += wcnt[i]; }
        g_part_sum[blk] = s;
        g_part_cnt[blk] = c;
        g_part_fg[blk]  = anyfg;
        __threadfence();
        unsigned old = atomicAdd(&g_done, 1u);
        s_islast = (old == NBLK - 1u);
        if (s_islast) g_done = 0;   // self-reset for graph replay
    }
    __syncthreads();
    if (!s_islast) return;

    // fused finalize (last block): per-batch fg slice range + masked sum
    __threadfence();
    int f = (t < NS) ? (g_part_fg[2 * t] | g_part_fg[2 * t + 1]) : 0;
    unsigned bal = __ballot_sync(0xffffffffu, f != 0);
    if (t < NS && lane == 0) s_fgw[wp] = bal;      // wp < 4 for t < 128
    __syncthreads();
    if (t < BB) {
        unsigned long long m = (unsigned long long)s_fgw[2 * t] |
                               ((unsigned long long)s_fgw[2 * t + 1] << 32);
        s_first[t] = m ? (__ffsll((long long)m) - 1) : 0;   // argmax(all-false)=0
        s_last[t]  = m ? (63 - __clzll((long long)m)) : (DD - 1);
    }
    __syncthreads();
    float ms = 0.0f, mc = 0.0f;
    if (t < NBLK) {
        int sl = t >> 1;
        int b  = sl >> 6, d = sl & (DD - 1);
        int in = (d >= s_first[b]) && (d <= s_last[b]);
        ms = in ? g_part_sum[t] : 0.0f;
        mc = g_part_cnt[t];
    }
    #pragma unroll
    for (int o = 16; o > 0; o >>= 1) {
        ms += __shfl_down_sync(0xffffffffu, ms, o);
        mc += __shfl_down_sync(0xffffffffu, mc, o);
    }
    if (lane == 0) { wsum[wp] = ms; wcnt[wp] = mc; }
    __syncthreads();
    if (t == 0) {
        float s = 0.0f, c = 0.0f;
        #pragma unroll
        for (int i = 0; i < NWARP; i++) { s += wsum[i]; c += wcnt[i]; }
        out[0] = s / c;
    }
}

extern "C" void kernel_launch(void* const* d_in, const int* in_sizes, int n_in,
                              void* d_out, int out_size)
{
    const float* yp = (const float*)d_in[0];
    const float* yt = (const float*)d_in[1];
    float* out = (float*)d_out;
    edt_kernel<<<NBLK, NT>>>(yp, yt, out);
}

// round 9
// speedup vs baseline: 1.5149x; 1.5149x over previous
#include <cuda_runtime.h>

#define BB 2
#define DD 64
#define HH 128
#define WW 128
#define NS (BB*DD)      // 128 slices
#define NBLK NS         // one block per slice
#define NT 512
#define NWARP 16
#define GR 10           // guard rows each side (zero-filled)
#define SROWS (HH + 2*GR)
#define SSTR 6          // words per stored row: [guardW-1, W0..W3, guardW4]

constexpr int count_tab() {
    int n = 0;
    for (int dr = -9; dr <= 9; ++dr)
        for (int dc = -9; dc <= 9; ++dc) {
            int d2 = dr * dr + dc * dc;
            if (d2 >= 1 && d2 <= 99) ++n;
        }
    return n;
}
constexpr int TABN = count_tab();           // 304
constexpr int count_groups() {
    int n = 0;
    for (int d2 = 1; d2 <= 99; ++d2) {
        bool any = false;
        for (int dr = -9; dr <= 9 && !any; ++dr)
            for (int dc = -9; dc <= 9; ++dc)
                if (dr * dr + dc * dc == d2) { any = true; break; }
        if (any) ++n;
    }
    return n;
}
constexpr int NG = count_groups();
constexpr int NBATCH = (NG + 3) / 4;

constexpr double csqrt_(double x) {
    double g = x > 1.0 ? x : 1.0;
    for (int i = 0; i < 60; ++i) g = 0.5 * (g + x / g);
    return g;
}
struct OffTab {
    signed char dr[TABN], dc[TABN];
    short gstart[NG], gcnt[NG];
    float sv[NG];
};
constexpr OffTab make_tab() {
    OffTab t{};
    int n = 0, gi = 0;
    for (int d2 = 1; d2 <= 99; ++d2) {
        int start = n;
        for (int dr = -9; dr <= 9; ++dr)
            for (int dc = -9; dc <= 9; ++dc)
                if (dr * dr + dc * dc == d2) {
                    t.dr[n] = (signed char)dr; t.dc[n] = (signed char)dc; ++n;
                }
        if (n > start) {
            t.gstart[gi] = (short)start;
            t.gcnt[gi]   = (short)(n - start);
            t.sv[gi]     = (float)csqrt_((double)d2);
            ++gi;
        }
    }
    return t;
}
__device__ constexpr OffTab TB = make_tab();

__device__ volatile float g_part_sum[NBLK];
__device__ volatile float g_part_cnt[NBLK];
__device__ volatile int   g_part_fg[NBLK];
__device__ unsigned int   g_done = 0;

// combined(px) = dist to nearest opposite-valued pixel (s binary => one EDT
// term always zero), clamped at 10. Bit-parallel: rows packed to 128-bit
// masks; per offset (dr,dc) the opposite mask for 32 pixels is one xor of a
// funnel-shifted neighbor row. The offset walk is FULLY UNROLLED with
// compile-time dr/dc (immediate shifts, CSE'd row loads) in batches of 4
// d2-groups with independent accumulators (ILP), one branch-free fold + one
// exit test per batch. found seeded with ~y_true so only contributing pixels
// gate the exit; unfound pixels contribute exactly the clamp value 10.
__global__ __launch_bounds__(NT)
void edt_kernel(const float* __restrict__ yp, const float* __restrict__ yt,
                float* __restrict__ out)
{
    __shared__ unsigned sS[SROWS][SSTR];
    __shared__ unsigned sY[HH][4];
    __shared__ float wsum[NWARP], wcnt[NWARP];
    __shared__ int s_islast;
    __shared__ unsigned s_fgw[4];
    __shared__ int s_first[BB], s_last[BB];

    const int slice = blockIdx.x;
    const int t = threadIdx.x;
    const int lane = t & 31, wp = t >> 5;
    const float* yps = yp + (size_t)slice * HH * WW;
    const float* yts = yt + (size_t)slice * HH * WW;

    // zero all stored words (guard rows + guard cols)
    for (int i = t; i < SROWS * SSTR; i += NT) ((unsigned*)sS)[i] = 0u;
    __syncthreads();

    // pack phase: one warp-ballot per (row, word); coalesced 128B loads
    for (int task = wp; task < HH * 4; task += NWARP) {
        int r = task >> 2, w = task & 3;
        unsigned ms = __ballot_sync(0xffffffffu, yps[r * WW + w * 32 + lane] > 0.7f);
        unsigned my = __ballot_sync(0xffffffffu, yts[r * WW + w * 32 + lane] != 0.0f);
        if (lane == 0) { sS[GR + r][1 + w] = ms; sY[r][w] = my; }
    }
    __syncthreads();

    // main phase: thread <-> (row, word), 32 pixels per thread
    const int r = t >> 2, w = t & 3;
    const unsigned self = sS[GR + r][1 + w];
    const unsigned ytm  = sY[r][w];
    const unsigned* rowbase = &sS[GR + r][0];
    int fgflag = (self != 0u);
    unsigned found = ~ytm;          // non-y_true pixels are don't-care
    float sum = 0.0f;

    #pragma unroll
    for (int bi = 0; bi < NBATCH; ++bi) {
        unsigned gorv[4] = {0u, 0u, 0u, 0u};
        #pragma unroll
        for (int q = 0; q < 4; ++q) {
            const int gi = bi * 4 + q;
            if (gi < NG) {
                #pragma unroll
                for (int k = 0; k < TB.gcnt[gi]; ++k) {
                    const int dr = (int)TB.dr[TB.gstart[gi] + k];
                    const int dc = (int)TB.dc[TB.gstart[gi] + k];
                    const unsigned* rw = rowbase + dr * SSTR;
                    unsigned sh, valid;
                    if (dc >= 0) {      // (W[w] >> dc) | (W[w+1] << (32-dc))
                        sh = __funnelshift_r(rw[1 + w], rw[2 + w], dc);
                        valid = (w == 3) ? (0xffffffffu >> dc) : 0xffffffffu;
                    } else {            // (W[w] << k) | (W[w-1] >> (32-k))
                        const int kk = -dc;
                        sh = __funnelshift_l(rw[w], rw[1 + w], kk);
                        valid = (w == 0) ? (0xffffffffu << kk) : 0xffffffffu;
                    }
                    unsigned rv = ((unsigned)(r + dr) < (unsigned)HH) ? 0xffffffffu : 0u;
                    gorv[q] |= (self ^ sh) & valid & rv;
                }
            }
        }
        #pragma unroll
        for (int q = 0; q < 4; ++q) {
            const int gi = bi * 4 + q;
            if (gi < NG) {
                unsigned nw = gorv[q] & ~found;   // fresh-per-group is exact:
                sum += TB.sv[gi] * (float)__popc(nw); // found absorbs earlier groups
                found |= nw;
            }
        }
        if (found == 0xffffffffu) break;
    }
    sum += 10.0f * (float)__popc(~found);   // unfound => dist >= 10 => clamp
    float cntf = (float)__popc(ytm);
    int anyfg = __syncthreads_or(fgflag);

    // block reduction (16 warps)
    #pragma unroll
    for (int o = 16; o > 0; o >>= 1) {
        sum  += __shfl_down_sync(0xffffffffu, sum,  o);
        cntf += __shfl_down_sync(0xffffffffu, cntf, o);
    }
    if (lane == 0) { wsum[wp] = sum; wcnt[wp] = cntf; }
    __syncthreads();
    if (t == 0) {
        float s = 0.0f, c = 0.0f;
        #pragma unroll
        for (int i = 0; i < NWARP; i++) { s += wsum[i]; c += wcnt[i]; }
        g_part_sum[slice] = s;
        g_part_cnt[slice] = c;
        g_part_fg[slice]  = anyfg;
        __threadfence();
        unsigned old = atomicAdd(&g_done, 1u);
        s_islast = (old == NBLK - 1u);
        if (s_islast) g_done = 0;   // self-reset for graph replay
    }
    __syncthreads();
    if (!s_islast) return;

    // fused finalize (last block): per-batch fg slice range + masked sum
    __threadfence();
    int f = (t < NS) ? g_part_fg[t] : 0;
    unsigned bal = __ballot_sync(0xffffffffu, f != 0);
    if (t < NS && lane == 0) s_fgw[wp] = bal;      // wp < 4 for t < 128
    __syncthreads();
    if (t < BB) {
        unsigned long long m = (unsigned long long)s_fgw[2 * t] |
                               ((unsigned long long)s_fgw[2 * t + 1] << 32);
        s_first[t] = m ? (__ffsll((long long)m) - 1) : 0;   // argmax(all-false)=0
        s_last[t]  = m ? (63 - __clzll((long long)m)) : (DD - 1);
    }
    __syncthreads();
    float ms = 0.0f, mc = 0.0f;
    if (t < NS) {
        int b = t >> 6, d = t & (DD - 1);
        int in = (d >= s_first[b]) && (d <= s_last[b]);
        ms = in ? g_part_sum[t] : 0.0f;
        mc = g_part_cnt[t];
    }
    #pragma unroll
    for (int o = 16; o > 0; o >>= 1) {
        ms += __shfl_down_sync(0xffffffffu, ms, o);
        mc += __shfl_down_sync(0xffffffffu, mc, o);
    }
    if (lane == 0) { wsum[wp] = ms; wcnt[wp] = mc; }
    __syncthreads();
    if (t == 0) {
        float s = 0.0f, c = 0.0f;
        #pragma unroll
        for (int i = 0; i < NWARP; i++) { s += wsum[i]; c += wcnt[i]; }
        out[0] = s / c;
    }
}

extern "C" void kernel_launch(void* const* d_in, const int* in_sizes, int n_in,
                              void* d_out, int out_size)
{
    const float* yp = (const float*)d_in[0];
    const float* yt = (const float*)d_in[1];
    float* out = (float*)d_out;
    edt_kernel<<<NBLK, NT>>>(yp, yt, out);
}

// round 10
// speedup vs baseline: 1.9065x; 1.2586x over previous
#include <cuda_runtime.h>

#define BB 2
#define DD 64
#define HH 128
#define WW 128
#define NS (BB*DD)      // 128 slices
#define NBLK NS         // one block per slice
#define NT 512
#define NWARP 16
#define GR 10           // guard rows each side (zero-filled)
#define SROWS (HH + 2*GR)
#define SSTR 6          // words per stored row: [guardW-1, W0..W3, guardW4]

constexpr int count_tab() {
    int n = 0;
    for (int dr = -9; dr <= 9; ++dr)
        for (int dc = -9; dc <= 9; ++dc) {
            int d2 = dr * dr + dc * dc;
            if (d2 >= 1 && d2 <= 99) ++n;
        }
    return n;
}
constexpr int TABN = count_tab();           // 304
constexpr int count_groups() {
    int n = 0;
    for (int d2 = 1; d2 <= 99; ++d2) {
        bool any = false;
        for (int dr = -9; dr <= 9 && !any; ++dr)
            for (int dc = -9; dc <= 9; ++dc)
                if (dr * dr + dc * dc == d2) { any = true; break; }
        if (any) ++n;
    }
    return n;
}
constexpr int NG = count_groups();
constexpr int NBATCH = (NG + 3) / 4;

constexpr double csqrt_(double x) {
    double g = x > 1.0 ? x : 1.0;
    for (int i = 0; i < 60; ++i) g = 0.5 * (g + x / g);
    return g;
}
struct OffTab {
    signed char dr[TABN], dc[TABN];
    short gstart[NG], gcnt[NG];
    float sv[NG];
};
constexpr OffTab make_tab() {
    OffTab t{};
    int n = 0, gi = 0;
    for (int d2 = 1; d2 <= 99; ++d2) {
        int start = n;
        for (int dr = -9; dr <= 9; ++dr)
            for (int dc = -9; dc <= 9; ++dc)
                if (dr * dr + dc * dc == d2) {
                    t.dr[n] = (signed char)dr; t.dc[n] = (signed char)dc; ++n;
                }
        if (n > start) {
            t.gstart[gi] = (short)start;
            t.gcnt[gi]   = (short)(n - start);
            t.sv[gi]     = (float)csqrt_((double)d2);
            ++gi;
        }
    }
    return t;
}
__device__ constexpr OffTab TB = make_tab();

__device__ volatile float g_part_sum[NBLK];
__device__ volatile float g_part_cnt[NBLK];
__device__ volatile int   g_part_fg[NBLK];
__device__ unsigned int   g_done = 0;

// compress 8 nibbles (one per byte of x, low 4 bits) into a 32-bit word,
// preserving pixel order: result bit (4j+i) = bit i of byte j.
__device__ __forceinline__ unsigned nib_compress(unsigned long long x) {
    x = (x | (x >> 4))  & 0x00FF00FF00FF00FFull;
    x = (x | (x >> 8))  & 0x0000FFFF0000FFFFull;
    x = (x | (x >> 16));
    return (unsigned)x;
}

// combined(px) = dist to nearest opposite-valued pixel (s binary => one EDT
// term always zero), clamped at 10. Bit-parallel: rows packed to 128-bit
// masks; per offset (dr,dc) the opposite mask for 32 pixels is one xor of a
// funnel-shifted neighbor row. Pack phase is MLP-8 batched float4 loads ->
// nibble staging -> u64 compress (no ballots: the input read is the real
// bottleneck). Offset walk fully unrolled, batches of 4 d2-groups with
// independent accumulators, one exit test per batch. found seeded with
// ~y_true; unfound pixels contribute exactly the clamp value 10.
__global__ __launch_bounds__(NT)
void edt_kernel(const float* __restrict__ yp, const float* __restrict__ yt,
                float* __restrict__ out)
{
    __shared__ unsigned sS[SROWS][SSTR];
    __shared__ unsigned sY[HH][4];
    __shared__ unsigned char pS[HH][32];
    __shared__ unsigned char pY[HH][32];
    __shared__ float wsum[NWARP], wcnt[NWARP];
    __shared__ int s_islast;
    __shared__ unsigned s_fgw[4];
    __shared__ int s_first[BB], s_last[BB];

    const int slice = blockIdx.x;
    const int t = threadIdx.x;
    const int lane = t & 31, wp = t >> 5;
    const float* yps = yp + (size_t)slice * HH * WW;
    const float* yts = yt + (size_t)slice * HH * WW;

    // zero guard words of sS
    for (int i = t; i < SROWS * SSTR; i += NT) ((unsigned*)sS)[i] = 0u;

    // ---- pack phase: MLP-8 float4 loads, nibble per lane, no ballots ----
    {
        const int prow0 = wp * 8;   // 16 warps x 8 rows = 128 rows
        float4 a[8];
        #pragma unroll
        for (int i = 0; i < 8; i++)
            a[i] = __ldg((const float4*)(yps + (size_t)(prow0 + i) * WW) + lane);
        #pragma unroll
        for (int i = 0; i < 8; i++) {
            unsigned n = (a[i].x > 0.7f ? 1u : 0u) | (a[i].y > 0.7f ? 2u : 0u)
                       | (a[i].z > 0.7f ? 4u : 0u) | (a[i].w > 0.7f ? 8u : 0u);
            pS[prow0 + i][lane] = (unsigned char)n;
        }
        #pragma unroll
        for (int i = 0; i < 8; i++)
            a[i] = __ldg((const float4*)(yts + (size_t)(prow0 + i) * WW) + lane);
        #pragma unroll
        for (int i = 0; i < 8; i++) {
            unsigned n = (a[i].x != 0.0f ? 1u : 0u) | (a[i].y != 0.0f ? 2u : 0u)
                       | (a[i].z != 0.0f ? 4u : 0u) | (a[i].w != 0.0f ? 8u : 0u);
            pY[prow0 + i][lane] = (unsigned char)n;
        }
    }
    __syncthreads();

    // ---- assemble: thread <-> (row, word), u64 nibble-compress ----
    const int r = t >> 2, w = t & 3;
    {
        unsigned long long x = *(const unsigned long long*)&pS[r][w * 8];
        sS[GR + r][1 + w] = nib_compress(x);
        unsigned long long y = *(const unsigned long long*)&pY[r][w * 8];
        sY[r][w] = nib_compress(y);
    }
    __syncthreads();

    // ---- main phase: thread <-> (row, word), 32 pixels per thread ----
    const unsigned self = sS[GR + r][1 + w];
    const unsigned ytm  = sY[r][w];
    const unsigned* rowbase = &sS[GR + r][0];
    int fgflag = (self != 0u);
    unsigned found = ~ytm;          // non-y_true pixels are don't-care
    float sum = 0.0f;

    #pragma unroll
    for (int bi = 0; bi < NBATCH; ++bi) {
        unsigned gorv[4] = {0u, 0u, 0u, 0u};
        #pragma unroll
        for (int q = 0; q < 4; ++q) {
            const int gi = bi * 4 + q;
            if (gi < NG) {
                #pragma unroll
                for (int k = 0; k < TB.gcnt[gi]; ++k) {
                    const int dr = (int)TB.dr[TB.gstart[gi] + k];
                    const int dc = (int)TB.dc[TB.gstart[gi] + k];
                    const unsigned* rw = rowbase + dr * SSTR;
                    unsigned sh, valid;
                    if (dc >= 0) {      // (W[w] >> dc) | (W[w+1] << (32-dc))
                        sh = __funnelshift_r(rw[1 + w], rw[2 + w], dc);
                        valid = (w == 3) ? (0xffffffffu >> dc) : 0xffffffffu;
                    } else {            // (W[w] << k) | (W[w-1] >> (32-k))
                        const int kk = -dc;
                        sh = __funnelshift_l(rw[w], rw[1 + w], kk);
                        valid = (w == 0) ? (0xffffffffu << kk) : 0xffffffffu;
                    }
                    unsigned rv = ((unsigned)(r + dr) < (unsigned)HH) ? 0xffffffffu : 0u;
                    gorv[q] |= (self ^ sh) & valid & rv;
                }
            }
        }
        #pragma unroll
        for (int q = 0; q < 4; ++q) {
            const int gi = bi * 4 + q;
            if (gi < NG) {
                unsigned nw = gorv[q] & ~found;       // fresh-per-group exact:
                sum += TB.sv[gi] * (float)__popc(nw); // found absorbs earlier
                found |= nw;
            }
        }
        if (found == 0xffffffffu) break;
    }
    sum += 10.0f * (float)__popc(~found);   // unfound => dist >= 10 => clamp
    float cntf = (float)__popc(ytm);
    int anyfg = __syncthreads_or(fgflag);

    // block reduction (16 warps)
    #pragma unroll
    for (int o = 16; o > 0; o >>= 1) {
        sum  += __shfl_down_sync(0xffffffffu, sum,  o);
        cntf += __shfl_down_sync(0xffffffffu, cntf, o);
    }
    if (lane == 0) { wsum[wp] = sum; wcnt[wp] = cntf; }
    __syncthreads();
    if (t == 0) {
        float s = 0.0f, c = 0.0f;
        #pragma unroll
        for (int i = 0; i < NWARP; i++) { s += wsum[i]; c += wcnt[i]; }
        g_part_sum[slice] = s;
        g_part_cnt[slice] = c;
        g_part_fg[slice]  = anyfg;
        __threadfence();
        unsigned old = atomicAdd(&g_done, 1u);
        s_islast = (old == NBLK - 1u);
        if (s_islast) g_done = 0;   // self-reset for graph replay
    }
    __syncthreads();
    if (!s_islast) return;

    // fused finalize (last block): per-batch fg slice range + masked sum
    __threadfence();
    int f = (t < NS) ? g_part_fg[t] : 0;
    unsigned bal = __ballot_sync(0xffffffffu, f != 0);
    if (t < NS && lane == 0) s_fgw[wp] = bal;      // wp < 4 for t < 128
    __syncthreads();
    if (t < BB) {
        unsigned long long m = (unsigned long long)s_fgw[2 * t] |
                               ((unsigned long long)s_fgw[2 * t + 1] << 32);
        s_first[t] = m ? (__ffsll((long long)m) - 1) : 0;   // argmax(all-false)=0
        s_last[t]  = m ? (63 - __clzll((long long)m)) : (DD - 1);
    }
    __syncthreads();
    float ms = 0.0f, mc = 0.0f;
    if (t < NS) {
        int b = t >> 6, d = t & (DD - 1);
        int in = (d >= s_first[b]) && (d <= s_last[b]);
        ms = in ? g_part_sum[t] : 0.0f;
        mc = g_part_cnt[t];
    }
    #pragma unroll
    for (int o = 16; o > 0; o >>= 1) {
        ms += __shfl_down_sync(0xffffffffu, ms, o);
        mc += __shfl_down_sync(0xffffffffu, mc, o);
    }
    if (lane == 0) { wsum[wp] = ms; wcnt[wp] = mc; }
    __syncthreads();
    if (t == 0) {
        float s = 0.0f, c = 0.0f;
        #pragma unroll
        for (int i = 0; i < NWARP; i++) { s += wsum[i]; c += wcnt[i]; }
        out[0] = s / c;
    }
}

extern "C" void kernel_launch(void* const* d_in, const int* in_sizes, int n_in,
                              void* d_out, int out_size)
{
    const float* yp = (const float*)d_in[0];
    const float* yt = (const float*)d_in[1];
    float* out = (float*)d_out;
    edt_kernel<<<NBLK, NT>>>(yp, yt, out);
}